// round 4
// baseline (speedup 1.0000x reference)
#include <cuda_runtime.h>

// Net_2095944040841: 3-layer LSTM (reference's buggy c-state wiring) on GB300.
// R4: column-split gates across 8 warps (2/SMSP) with partial-sum combine fused
// into the update phase. 6 barriers/step. Bias folded into accumulator init.

#define T_LEN 1024
#define IN_D  20
#define HIDN  50
#define OUT_D 8
#define NB    4
#define NCTA  128
#define NTH   256

// shared memory layout (float offsets)
#define WA_STR 76            // cell1 row: 20 fused-x + 50 Whh1 + 6 zero pad (304B stride)
#define WA_OFF 0             // 200 x 76
#define WB_OFF 15200         // 200 x 100  [Wih2 | Whh2]
#define WC_OFF 35200         // 200 x 100  [Wih3 | Whh3]
#define W2_OFF 55200         // 8 x 50
#define IN1_OFF 55600        // 38 pairs [pair][batch][2]: x p0-9, h1 p10-34, pad p35-37
#define ST_OFF  55904        // 75 pairs: h1 +0, h2 +200, h3 +400
#define PART0_OFF 56504      // 200 rows x 4 batches partials, column-half 0
#define PART1_OFF 57304      // column-half 1
#define SMEM_FLT 58104       // 232,416 bytes

typedef unsigned long long ull;

static __device__ __forceinline__ void upk(ull v, float &a, float &b) {
    asm("mov.b64 {%0,%1}, %2;" : "=f"(a), "=f"(b) : "l"(v));
}
static __device__ __forceinline__ ull fma2(ull a, ull b, ull c) {
    ull d; asm("fma.rn.f32x2 %0, %1, %2, %3;" : "=l"(d) : "l"(a), "l"(b), "l"(c)); return d;
}
static __device__ __forceinline__ float sigm(float x) {
    return __fdividef(1.f, 1.f + __expf(-x));
}
static __device__ __forceinline__ float tanh_(float x) {
    x = fminf(fmaxf(x, -15.f), 15.f);
    float e = __expf(-2.f * x);
    return __fdividef(1.f - e, 1.f + e);
}

// Partial GEMV for 2 rows x 4 batches over column chunks [KK0,KK1) (1 chunk = 4 cols).
// Bias is folded into the accumulator via zero-extended init (lo lane only).
template<int KK0, int KK1>
static __device__ __forceinline__ void gate_partial(
    const float* __restrict__ w0row, const float* __restrict__ w1row,
    float bias0, float bias1,
    const float* __restrict__ in, float* __restrict__ part,
    int r0, int r1)
{
    const ulonglong2* w0q = reinterpret_cast<const ulonglong2*>(w0row) + KK0;
    const ulonglong2* w1q = reinterpret_cast<const ulonglong2*>(w1row) + KK0;
    const ulonglong2* q   = reinterpret_cast<const ulonglong2*>(in) + 4 * KK0;
    ull b0z = (ull)__float_as_uint(bias0);   // packed (bias, 0)
    ull b1z = (ull)__float_as_uint(bias1);
    ull a00 = b0z, a01 = b0z, a02 = b0z, a03 = b0z;
    ull a10 = b1z, a11 = b1z, a12 = b1z, a13 = b1z;
#pragma unroll
    for (int kk = 0; kk < KK1 - KK0; kk++) {
        ulonglong2 w0 = w0q[kk], w1 = w1q[kk];
        ulonglong2 q0 = q[4*kk+0], q1 = q[4*kk+1], q2 = q[4*kk+2], q3 = q[4*kk+3];
        a00 = fma2(w0.x, q0.x, a00); a01 = fma2(w0.x, q0.y, a01);
        a02 = fma2(w0.x, q1.x, a02); a03 = fma2(w0.x, q1.y, a03);
        a10 = fma2(w1.x, q0.x, a10); a11 = fma2(w1.x, q0.y, a11);
        a12 = fma2(w1.x, q1.x, a12); a13 = fma2(w1.x, q1.y, a13);
        a00 = fma2(w0.y, q2.x, a00); a01 = fma2(w0.y, q2.y, a01);
        a02 = fma2(w0.y, q3.x, a02); a03 = fma2(w0.y, q3.y, a03);
        a10 = fma2(w1.y, q2.x, a10); a11 = fma2(w1.y, q2.y, a11);
        a12 = fma2(w1.y, q3.x, a12); a13 = fma2(w1.y, q3.y, a13);
    }
    float lo, hi; float4 p0, p1;
    upk(a00, lo, hi); p0.x = lo + hi;  upk(a01, lo, hi); p0.y = lo + hi;
    upk(a02, lo, hi); p0.z = lo + hi;  upk(a03, lo, hi); p0.w = lo + hi;
    upk(a10, lo, hi); p1.x = lo + hi;  upk(a11, lo, hi); p1.y = lo + hi;
    upk(a12, lo, hi); p1.z = lo + hi;  upk(a13, lo, hi); p1.w = lo + hi;
    reinterpret_cast<float4*>(part)[r0] = p0;
    reinterpret_cast<float4*>(part)[r1] = p1;
}

// Combine halves + activate + LSTM state update for unit u, batches 2bp..2bp+1.
static __device__ __forceinline__ void finish_cell(
    float* __restrict__ smp, int cell, int u, int bp,
    float* __restrict__ c1s, float* __restrict__ czs)
{
    const float2* P0 = reinterpret_cast<const float2*>(smp + PART0_OFF);
    const float2* P1 = reinterpret_cast<const float2*>(smp + PART1_OFF);
    const int ii = u * 2 + bp, fi = (u + 50) * 2 + bp,
              gi = (u + 100) * 2 + bp, oi = (u + 150) * 2 + bp;
    float2 pa, pb;
    pa = P0[ii]; pb = P1[ii];
    float iv0 = sigm(pa.x + pb.x), iv1 = sigm(pa.y + pb.y);
    pa = P0[fi]; pb = P1[fi];
    float fv0 = sigm(pa.x + pb.x), fv1 = sigm(pa.y + pb.y);
    pa = P0[gi]; pb = P1[gi];
    float gv0 = tanh_(pa.x + pb.x), gv1 = tanh_(pa.y + pb.y);
    pa = P0[oi]; pb = P1[oi];
    float ov0 = sigm(pa.x + pb.x), ov1 = sigm(pa.y + pb.y);

    float h0, h1v;
    if (cell == 0) {
        c1s[0] = fv0 * c1s[0] + iv0 * gv0;  h0  = ov0 * tanh_(c1s[0]);
        c1s[1] = fv1 * c1s[1] + iv1 * gv1;  h1v = ov1 * tanh_(c1s[1]);
    } else if (cell == 1) {
        float ca = fv0 * czs[0] + iv0 * gv0;  h0  = ov0 * tanh_(ca);
        float cb = fv1 * czs[1] + iv1 * gv1;  h1v = ov1 * tanh_(cb);
    } else {
        czs[0] = iv0 * gv0;  h0  = ov0 * tanh_(czs[0]);
        czs[1] = iv1 * gv1;  h1v = ov1 * tanh_(czs[1]);
    }
    const int up = u >> 1, us = u & 1, bb = 2 * bp;
    const int dst = (cell == 0) ? ST_OFF : (cell == 1 ? ST_OFF + 200 : ST_OFF + 400);
    smp[dst + up * 8 + 2 * bb + us]       = h0;
    smp[dst + up * 8 + 2 * (bb + 1) + us] = h1v;
    if (cell == 0) {   // h1 also feeds next step's cell1 input
        smp[IN1_OFF + (10 + up) * 8 + 2 * bb + us]       = h0;
        smp[IN1_OFF + (10 + up) * 8 + 2 * (bb + 1) + us] = h1v;
    }
}

static __device__ __forceinline__ void outproj(
    const float* __restrict__ smp, float* __restrict__ out,
    int b0, int j, int t, float bias)
{
    const int ob = j >> 3, oo = j & 7;
    const float2* w2 = reinterpret_cast<const float2*>(smp + W2_OFF + oo * HIDN);
    const float2* h3 = reinterpret_cast<const float2*>(smp + ST_OFF + 400);
    float acc = bias;
#pragma unroll
    for (int p = 0; p < 25; p++) {
        float2 w = w2[p];
        float2 h = h3[p * 4 + ob];        // units 2p,2p+1 of batch ob
        acc = fmaf(w.x, h.x, fmaf(w.y, h.y, acc));
    }
    out[((size_t)(b0 + ob) * T_LEN + t) * OUT_D + oo] = acc;
}

extern __shared__ float sm[];

__global__ void __launch_bounds__(NTH, 1)
lstm_persist_kernel(const float* __restrict__ x,
                    const float* __restrict__ W1,   const float* __restrict__ b1,
                    const float* __restrict__ Wih1, const float* __restrict__ Whh1,
                    const float* __restrict__ bih1, const float* __restrict__ bhh1,
                    const float* __restrict__ Wih2, const float* __restrict__ Whh2,
                    const float* __restrict__ bih2, const float* __restrict__ bhh2,
                    const float* __restrict__ Wih3, const float* __restrict__ Whh3,
                    const float* __restrict__ bih3, const float* __restrict__ bhh3,
                    const float* __restrict__ W2,   const float* __restrict__ b2,
                    float* __restrict__ out)
{
    const int tid  = threadIdx.x;
    const int b0   = blockIdx.x * NB;
    const int lane = tid & 31, wrp = tid >> 5;

    // ---------------- init: build fused weights in SMEM ----------------
    for (int i = tid; i < HIDN * IN_D; i += NTH) sm[PART0_OFF + i] = W1[i];  // stage W1
    __syncthreads();

    // WA x-part: Wc[r][k] = sum_j Wih1[r][j] * W1[j][k]
    for (int i = tid; i < 200 * IN_D; i += NTH) {
        int r = i / IN_D, k = i % IN_D;
        float acc = 0.f;
#pragma unroll 10
        for (int j = 0; j < HIDN; j++)
            acc += Wih1[r * HIDN + j] * sm[PART0_OFF + j * IN_D + k];
        sm[WA_OFF + r * WA_STR + k] = acc;
    }
    // WA h-part + zero pad (cols 20..75)
    for (int i = tid; i < 200 * 56; i += NTH) {
        int r = i / 56, c = i % 56;
        sm[WA_OFF + r * WA_STR + IN_D + c] = (c < HIDN) ? Whh1[r * HIDN + c] : 0.f;
    }
    // WB = [Wih2 | Whh2], WC = [Wih3 | Whh3]
    for (int i = tid; i < 200 * 100; i += NTH) {
        int r = i / 100, c = i % 100;
        sm[WB_OFF + i] = (c < HIDN) ? Wih2[r * HIDN + c] : Whh2[r * HIDN + c - HIDN];
        sm[WC_OFF + i] = (c < HIDN) ? Wih3[r * HIDN + c] : Whh3[r * HIDN + c - HIDN];
    }
    for (int i = tid; i < OUT_D * HIDN; i += NTH) sm[W2_OFF + i] = W2[i];
    __syncthreads();   // W1 staging reads complete

    // zero IN1 (beyond x slots), ST, PART
    for (int i = 80 + tid; i < 304; i += NTH) sm[IN1_OFF + i] = 0.f;
    for (int i = tid; i < 600;  i += NTH) sm[ST_OFF + i]    = 0.f;
    for (int i = tid; i < 1600; i += NTH) sm[PART0_OFF + i] = 0.f;
    if (tid < NB * IN_D) {
        int b = tid / IN_D, k = tid % IN_D;
        sm[IN1_OFF + (k >> 1) * 8 + 2 * b + (k & 1)] =
            x[((size_t)(b0 + b) * T_LEN) * IN_D + k];
    }
    __syncthreads();

    // ---------------- role setup ----------------
    const bool isgate = (lane < 25);
    const int  half   = wrp >> 2;                 // column half 0/1
    const int  g      = (wrp & 3) * 25 + lane;    // 0..99 -> rows g, g+100
    const bool isfin  = isgate && (half == 0);    // finishers: warps 0-3, lanes 0-24
    const int  fu = g >> 1, fbp = g & 1;          // finisher unit / batch-pair
    const bool ishelp = (lane >= 25);
    const int  hl = lane - 25;                    // 0..6
    const int  hx = (wrp - 4) * 7 + hl;           // x-prefetch id (warps 4-7): 0..27
    const int  hj = wrp * 7 + hl;                 // out-proj id (warps 0-3): 0..27

    // per-thread fused biases (registers; half-0 gate threads only)
    float ba0 = 0.f, ba1 = 0.f, bb0 = 0.f, bb1 = 0.f, bc0 = 0.f, bc1 = 0.f;
    if (isfin) {
        ba0 = bih1[g] + bhh1[g];           ba1 = bih1[g + 100] + bhh1[g + 100];
        for (int j = 0; j < HIDN; j++) {
            ba0 += Wih1[g * HIDN + j] * b1[j];
            ba1 += Wih1[(g + 100) * HIDN + j] * b1[j];
        }
        bb0 = bih2[g] + bhh2[g];           bb1 = bih2[g + 100] + bhh2[g + 100];
        bc0 = bih3[g] + bhh3[g];           bc1 = bih3[g + 100] + bhh3[g + 100];
    }
    float b2r0 = 0.f, b2r1 = 0.f;
    if (ishelp && wrp < 4) {
        b2r0 = b2[hj & 7];
        if (hj < 4) b2r1 = b2[(hj + 28) & 7];
    }

    const float* wa0 = sm + WA_OFF + g * WA_STR;
    const float* wa1 = sm + WA_OFF + (g + 100) * WA_STR;
    const float* wb0 = sm + WB_OFF + g * 100;
    const float* wb1 = sm + WB_OFF + (g + 100) * 100;
    const float* wc0 = sm + WC_OFF + g * 100;
    const float* wc1 = sm + WC_OFF + (g + 100) * 100;

    float c1s[2] = {0.f, 0.f};   // cell1 state (this unit, 2 batches)
    float czs[2] = {0.f, 0.f};   // carries cell3's c_new (ref bug: acts as c2)

    // ---------------- main recurrent loop ----------------
    for (int t = 0; t < T_LEN; t++) {
        float xv0 = 0.f, xv1 = 0.f, xv2 = 0.f;
        const bool xl = (t + 1 < T_LEN);

        // P1 cell1 || helpers: x(t+1) prefetch (w4-7), out(t-1) (w0-3)
        if (isgate) {
            if (half == 0)
                gate_partial<0, 9>(wa0, wa1, ba0, ba1, sm + IN1_OFF, sm + PART0_OFF, g, g + 100);
            else
                gate_partial<9, 19>(wa0, wa1, 0.f, 0.f, sm + IN1_OFF, sm + PART1_OFF, g, g + 100);
        } else if (wrp >= 4) {
            if (xl) {
                { int e = hx;      int b = e / IN_D, k = e % IN_D;
                  xv0 = x[((size_t)(b0 + b) * T_LEN + t + 1) * IN_D + k]; }
                { int e = hx + 28; int b = e / IN_D, k = e % IN_D;
                  xv1 = x[((size_t)(b0 + b) * T_LEN + t + 1) * IN_D + k]; }
                if (hx + 56 < 80) {
                  int e = hx + 56; int b = e / IN_D, k = e % IN_D;
                  xv2 = x[((size_t)(b0 + b) * T_LEN + t + 1) * IN_D + k]; }
            }
        } else {
            if (t > 0) {
                outproj(sm, out, b0, hj, t - 1, b2r0);
                if (hj < 4) outproj(sm, out, b0, hj + 28, t - 1, b2r1);
            }
        }
        __syncthreads();

        // P2 cell1: finish+update h1 || helpers store x(t+1)
        if (isfin) {
            finish_cell(sm, 0, fu, fbp, c1s, czs);
        } else if (ishelp && wrp >= 4 && xl) {
            { int e = hx;      int b = e / IN_D, k = e % IN_D;
              sm[IN1_OFF + (k >> 1) * 8 + 2 * b + (k & 1)] = xv0; }
            { int e = hx + 28; int b = e / IN_D, k = e % IN_D;
              sm[IN1_OFF + (k >> 1) * 8 + 2 * b + (k & 1)] = xv1; }
            if (hx + 56 < 80) {
              int e = hx + 56; int b = e / IN_D, k = e % IN_D;
              sm[IN1_OFF + (k >> 1) * 8 + 2 * b + (k & 1)] = xv2; }
        }
        __syncthreads();

        // P1 cell2: gates from [h1 | h2]
        if (isgate) {
            if (half == 0)
                gate_partial<0, 13>(wb0, wb1, bb0, bb1, sm + ST_OFF, sm + PART0_OFF, g, g + 100);
            else
                gate_partial<13, 25>(wb0, wb1, 0.f, 0.f, sm + ST_OFF, sm + PART1_OFF, g, g + 100);
        }
        __syncthreads();

        // P2 cell2: finish+update h2 (state = cz from prev step's cell3)
        if (isfin) finish_cell(sm, 1, fu, fbp, c1s, czs);
        __syncthreads();

        // P1 cell3: gates from [h2 | h3] (c3 input always 0)
        if (isgate) {
            if (half == 0)
                gate_partial<0, 13>(wc0, wc1, bc0, bc1, sm + ST_OFF + 200, sm + PART0_OFF, g, g + 100);
            else
                gate_partial<13, 25>(wc0, wc1, 0.f, 0.f, sm + ST_OFF + 200, sm + PART1_OFF, g, g + 100);
        }
        __syncthreads();

        // P2 cell3: c_new = i*g; cz <- c_new; h3
        if (isfin) finish_cell(sm, 2, fu, fbp, c1s, czs);
        __syncthreads();
    }

    // tail: out-projection for the final step
    if (ishelp && wrp < 4) {
        outproj(sm, out, b0, hj, T_LEN - 1, b2r0);
        if (hj < 4) outproj(sm, out, b0, hj + 28, T_LEN - 1, b2r1);
    }
}

extern "C" void kernel_launch(void* const* d_in, const int* in_sizes, int n_in,
                              void* d_out, int out_size)
{
    const float* x    = (const float*)d_in[0];
    const float* W1   = (const float*)d_in[1];
    const float* b1   = (const float*)d_in[2];
    const float* Wih1 = (const float*)d_in[3];
    const float* Whh1 = (const float*)d_in[4];
    const float* bih1 = (const float*)d_in[5];
    const float* bhh1 = (const float*)d_in[6];
    const float* Wih2 = (const float*)d_in[7];
    const float* Whh2 = (const float*)d_in[8];
    const float* bih2 = (const float*)d_in[9];
    const float* bhh2 = (const float*)d_in[10];
    const float* Wih3 = (const float*)d_in[11];
    const float* Whh3 = (const float*)d_in[12];
    const float* bih3 = (const float*)d_in[13];
    const float* bhh3 = (const float*)d_in[14];
    const float* W2   = (const float*)d_in[15];
    const float* b2   = (const float*)d_in[16];
    float* out = (float*)d_out;

    const int smem_bytes = SMEM_FLT * sizeof(float);  // 232,416
    cudaFuncSetAttribute(lstm_persist_kernel,
                         cudaFuncAttributeMaxDynamicSharedMemorySize, smem_bytes);

    lstm_persist_kernel<<<NCTA, NTH, smem_bytes>>>(
        x, W1, b1, Wih1, Whh1, bih1, bhh1,
        Wih2, Whh2, bih2, bhh2, Wih3, Whh3, bih3, bhh3,
        W2, b2, out);
}